// round 2
// baseline (speedup 1.0000x reference)
#include <cuda_runtime.h>
#include <cuda_bf16.h>
#include <cstdint>

#define NN 50000
#define NE 800000
#define FIN 128
#define HC 128      // HEADS*HID = 4*32
#define NH 4
#define CH 32
#define NOUT 32

// ------------------------- device scratch (no allocation allowed) -------------------------
__device__ float g_hproj[(size_t)NN * HC];
__device__ float g_hskip[(size_t)NN * HC];
__device__ float g_feat1[(size_t)NN * HC];
__device__ float g_feat2[(size_t)NN * HC];
__device__ float g_hskip32[(size_t)NN * NOUT];
__device__ float g_als[(size_t)NN * NH];
__device__ float g_ald[(size_t)NN * NH];
__device__ int   g_deg[NN];
__device__ int   g_cursor[NN];
__device__ int   g_rowptr[NN + 1];
__device__ int   g_csr[NE];

// Buffer selectors so the host never needs cudaGetSymbolAddress.
// 0 = external pointer argument, otherwise a named __device__ buffer.
#define SEL_EXT     0
#define SEL_HPROJ   1
#define SEL_HSKIP   2
#define SEL_FEAT1   3
#define SEL_FEAT2   4
#define SEL_HSKIP32 5

__device__ __forceinline__ float* selbuf(int sel, float* ext) {
    switch (sel) {
        case SEL_HPROJ:   return g_hproj;
        case SEL_HSKIP:   return g_hskip;
        case SEL_FEAT1:   return g_feat1;
        case SEL_FEAT2:   return g_feat2;
        case SEL_HSKIP32: return g_hskip32;
        default:          return ext;
    }
}
__device__ __forceinline__ const float* selbuf_c(int sel, const float* ext) {
    return selbuf(sel, (float*)ext);
}

// ------------------------- CSR build -------------------------
__global__ void zero_kernel() {
    int i = blockIdx.x * blockDim.x + threadIdx.x;
    if (i < NN) { g_deg[i] = 0; g_cursor[i] = 0; }
}

__global__ void count_kernel(const int* __restrict__ dst) {
    int i = blockIdx.x * blockDim.x + threadIdx.x;
    if (i < NE) atomicAdd(&g_deg[dst[i]], 1);
}

// exclusive scan of g_deg into g_rowptr, g_rowptr[NN]=total. Single block.
__global__ void scan_kernel() {
    __shared__ int sh[1024];
    __shared__ int carry;
    if (threadIdx.x == 0) carry = 0;
    __syncthreads();
    for (int base = 0; base < NN; base += 1024) {
        int i = base + threadIdx.x;
        int v = (i < NN) ? g_deg[i] : 0;
        sh[threadIdx.x] = v;
        __syncthreads();
        for (int off = 1; off < 1024; off <<= 1) {
            int t = 0;
            if ((int)threadIdx.x >= off) t = sh[threadIdx.x - off];
            __syncthreads();
            sh[threadIdx.x] += t;
            __syncthreads();
        }
        if (i < NN) g_rowptr[i] = carry + sh[threadIdx.x] - v;
        __syncthreads();
        if (threadIdx.x == 0) carry += sh[1023];
        __syncthreads();
    }
    if (threadIdx.x == 0) g_rowptr[NN] = carry;
}

__global__ void scatter_kernel(const int* __restrict__ src, const int* __restrict__ dst) {
    int i = blockIdx.x * blockDim.x + threadIdx.x;
    if (i < NE) {
        int d = dst[i];
        int pos = g_rowptr[d] + atomicAdd(&g_cursor[d], 1);
        g_csr[pos] = src[i];
    }
}

// ------------------------- SGEMM -------------------------
// C[M,N] = A[M,K] @ B[K,N] (+ bias[N] if bias != nullptr)
template <int BM, int BN, int BK, int TM, int TN>
__global__ void sgemm_kernel(const float* __restrict__ Aext, int Asel,
                             const float* __restrict__ B,
                             const float* __restrict__ bias,
                             float* __restrict__ Cext, int Csel,
                             int M, int N, int K) {
    const float* A = selbuf_c(Asel, Aext);
    float* C = selbuf(Csel, Cext);
    constexpr int NT = (BM / TM) * (BN / TN);
    __shared__ float As[BK][BM + 4];
    __shared__ float Bs[BK][BN];
    int tid = threadIdx.x;
    int m0 = blockIdx.y * BM;
    int n0 = blockIdx.x * BN;
    int tx = tid % (BN / TN);
    int ty = tid / (BN / TN);

    float acc[TM][TN];
#pragma unroll
    for (int i = 0; i < TM; i++)
#pragma unroll
        for (int j = 0; j < TN; j++) acc[i][j] = 0.f;

    for (int k0 = 0; k0 < K; k0 += BK) {
        // load A tile (BM x BK), store transposed
        for (int i = tid; i < BM * BK / 4; i += NT) {
            int r = i / (BK / 4);
            int c = (i % (BK / 4)) * 4;
            float4 v = make_float4(0.f, 0.f, 0.f, 0.f);
            if (m0 + r < M) v = *(const float4*)&A[(size_t)(m0 + r) * K + k0 + c];
            As[c + 0][r] = v.x;
            As[c + 1][r] = v.y;
            As[c + 2][r] = v.z;
            As[c + 3][r] = v.w;
        }
        // load B tile (BK x BN)
        for (int i = tid; i < BK * BN / 4; i += NT) {
            int r = i / (BN / 4);
            int c = (i % (BN / 4)) * 4;
            float4 v = *(const float4*)&B[(size_t)(k0 + r) * N + n0 + c];
            *(float4*)&Bs[r][c] = v;
        }
        __syncthreads();
#pragma unroll
        for (int k = 0; k < BK; k++) {
            float a[TM], b[TN];
#pragma unroll
            for (int i = 0; i < TM; i++) a[i] = As[k][ty * TM + i];
#pragma unroll
            for (int j = 0; j < TN; j++) b[j] = Bs[k][tx * TN + j];
#pragma unroll
            for (int i = 0; i < TM; i++)
#pragma unroll
                for (int j = 0; j < TN; j++) acc[i][j] += a[i] * b[j];
        }
        __syncthreads();
    }
#pragma unroll
    for (int i = 0; i < TM; i++) {
        int row = m0 + ty * TM + i;
        if (row < M) {
#pragma unroll
            for (int j = 0; j < TN; j++) {
                int col = n0 + tx * TN + j;
                float v = acc[i][j];
                if (bias) v += __ldg(&bias[col]);
                C[(size_t)row * N + col] = v;
            }
        }
    }
}

// ------------------------- attention logits -------------------------
// g_als[n,h] = sum_c g_hproj[n,h*32+c]*aS[h,c];  g_ald likewise
__global__ void al_kernel(const float* __restrict__ aS, const float* __restrict__ aD) {
    int idx = blockIdx.x * blockDim.x + threadIdx.x;
    if (idx >= NN * NH) return;
    int n = idx >> 2;
    int h = idx & 3;
    const float* hp = &g_hproj[(size_t)n * HC + h * CH];
    const float* as = &aS[h * CH];
    const float* ad = &aD[h * CH];
    float s1 = 0.f, s2 = 0.f;
#pragma unroll
    for (int c = 0; c < CH; c += 4) {
        float4 hv = *(const float4*)&hp[c];
        float4 av = __ldg((const float4*)&as[c]);
        float4 dv = __ldg((const float4*)&ad[c]);
        s1 += hv.x * av.x + hv.y * av.y + hv.z * av.z + hv.w * av.w;
        s2 += hv.x * dv.x + hv.y * dv.y + hv.z * dv.z + hv.w * dv.w;
    }
    g_als[idx] = s1;
    g_ald[idx] = s2;
}

__device__ __forceinline__ float lrelu(float x) { return x > 0.f ? x : 0.2f * x; }

// ------------------------- aggregation (softmax + weighted sum) -------------------------
// one warp per destination node. mode 0: concat+bias+skip+ELU -> out[N,128]
// mode 1: head-mean + bias + skip + L2-normalize -> out[N,32]
__global__ void agg_kernel(int skipsel, const float* __restrict__ bias,
                           float* __restrict__ outext, int outsel, int mode) {
    const float* hskip = selbuf_c(skipsel, nullptr);
    float* outp = selbuf(outsel, outext);
    const int WPB = 8;
    __shared__ float sh_alpha[WPB][32][4];
    __shared__ int sh_src[WPB][32];
    int w = threadIdx.x >> 5;
    int lane = threadIdx.x & 31;
    int n = blockIdx.x * WPB + w;
    if (n >= NN) return;
    int beg = g_rowptr[n], end = g_rowptr[n + 1];
    float4 ad = *(const float4*)&g_ald[(size_t)n * 4];

    // pass 1: per-head max
    float mx0 = -1e30f, mx1 = -1e30f, mx2 = -1e30f, mx3 = -1e30f;
    for (int j = beg + lane; j < end; j += 32) {
        int s = __ldg(&g_csr[j]);
        float4 a = __ldg((const float4*)&g_als[(size_t)s * 4]);
        mx0 = fmaxf(mx0, lrelu(a.x + ad.x));
        mx1 = fmaxf(mx1, lrelu(a.y + ad.y));
        mx2 = fmaxf(mx2, lrelu(a.z + ad.z));
        mx3 = fmaxf(mx3, lrelu(a.w + ad.w));
    }
#pragma unroll
    for (int o = 16; o > 0; o >>= 1) {
        mx0 = fmaxf(mx0, __shfl_xor_sync(0xffffffffu, mx0, o));
        mx1 = fmaxf(mx1, __shfl_xor_sync(0xffffffffu, mx1, o));
        mx2 = fmaxf(mx2, __shfl_xor_sync(0xffffffffu, mx2, o));
        mx3 = fmaxf(mx3, __shfl_xor_sync(0xffffffffu, mx3, o));
    }
    // pass 2: sum of exp
    float s0 = 0.f, s1 = 0.f, s2 = 0.f, s3 = 0.f;
    for (int j = beg + lane; j < end; j += 32) {
        int s = __ldg(&g_csr[j]);
        float4 a = __ldg((const float4*)&g_als[(size_t)s * 4]);
        s0 += __expf(lrelu(a.x + ad.x) - mx0);
        s1 += __expf(lrelu(a.y + ad.y) - mx1);
        s2 += __expf(lrelu(a.z + ad.z) - mx2);
        s3 += __expf(lrelu(a.w + ad.w) - mx3);
    }
#pragma unroll
    for (int o = 16; o > 0; o >>= 1) {
        s0 += __shfl_xor_sync(0xffffffffu, s0, o);
        s1 += __shfl_xor_sync(0xffffffffu, s1, o);
        s2 += __shfl_xor_sync(0xffffffffu, s2, o);
        s3 += __shfl_xor_sync(0xffffffffu, s3, o);
    }
    float inv0 = 1.f / (s0 + 1e-16f);
    float inv1 = 1.f / (s1 + 1e-16f);
    float inv2 = 1.f / (s2 + 1e-16f);
    float inv3 = 1.f / (s3 + 1e-16f);

    // pass 3: weighted gather of hproj[src]
    float acc0 = 0.f, acc1 = 0.f, acc2 = 0.f, acc3 = 0.f;
    for (int base = beg; base < end; base += 32) {
        int j = base + lane;
        if (j < end) {
            int sr = g_csr[j];
            sh_src[w][lane] = sr;
            float4 a = __ldg((const float4*)&g_als[(size_t)sr * 4]);
            sh_alpha[w][lane][0] = __expf(lrelu(a.x + ad.x) - mx0) * inv0;
            sh_alpha[w][lane][1] = __expf(lrelu(a.y + ad.y) - mx1) * inv1;
            sh_alpha[w][lane][2] = __expf(lrelu(a.z + ad.z) - mx2) * inv2;
            sh_alpha[w][lane][3] = __expf(lrelu(a.w + ad.w) - mx3) * inv3;
        }
        __syncwarp();
        int cnt = min(32, end - base);
        for (int k = 0; k < cnt; k++) {
            int sr = sh_src[w][k];
            const float* hp = &g_hproj[(size_t)sr * HC];
            float a0 = sh_alpha[w][k][0];
            float a1 = sh_alpha[w][k][1];
            float a2 = sh_alpha[w][k][2];
            float a3 = sh_alpha[w][k][3];
            acc0 += a0 * hp[lane];
            acc1 += a1 * hp[32 + lane];
            acc2 += a2 * hp[64 + lane];
            acc3 += a3 * hp[96 + lane];
        }
        __syncwarp();
    }

    if (mode == 0) {
        float accs[4] = {acc0, acc1, acc2, acc3};
#pragma unroll
        for (int h = 0; h < 4; h++) {
            int c = h * 32 + lane;
            float v = accs[h] + __ldg(&bias[c]) + hskip[(size_t)n * HC + c];
            v = v > 0.f ? v : expm1f(v);
            outp[(size_t)n * HC + c] = v;
        }
    } else {
        float v = 0.25f * (acc0 + acc1 + acc2 + acc3) + __ldg(&bias[lane]) +
                  hskip[(size_t)n * NOUT + lane];
        float ss = v * v;
#pragma unroll
        for (int o = 16; o > 0; o >>= 1) ss += __shfl_xor_sync(0xffffffffu, ss, o);
        float r = sqrtf(ss);
        outp[(size_t)n * NOUT + lane] = v / fmaxf(r, 1e-12f);
    }
}

// ------------------------- launch -------------------------
extern "C" void kernel_launch(void* const* d_in, const int* in_sizes, int n_in,
                              void* d_out, int out_size) {
    const float* x = (const float*)d_in[0];
    const int* ei = (const int*)d_in[1];
    const int* src = ei;
    const int* dst = ei + NE;
    const float* W0 = (const float*)d_in[2];
    const float* aS0 = (const float*)d_in[3];
    const float* aD0 = (const float*)d_in[4];
    const float* b0 = (const float*)d_in[5];
    const float* Ws0 = (const float*)d_in[6];
    const float* bs0 = (const float*)d_in[7];
    const float* W1 = (const float*)d_in[8];
    const float* aS1 = (const float*)d_in[9];
    const float* aD1 = (const float*)d_in[10];
    const float* b1 = (const float*)d_in[11];
    const float* Ws1 = (const float*)d_in[12];
    const float* bs1 = (const float*)d_in[13];
    const float* W2 = (const float*)d_in[14];
    const float* aS2 = (const float*)d_in[15];
    const float* aD2 = (const float*)d_in[16];
    const float* b2 = (const float*)d_in[17];
    const float* Ws2 = (const float*)d_in[18];
    const float* bs2 = (const float*)d_in[19];
    float* out = (float*)d_out;

    // ---- CSR build ----
    zero_kernel<<<(NN + 255) / 256, 256>>>();
    count_kernel<<<(NE + 255) / 256, 256>>>(dst);
    scan_kernel<<<1, 1024>>>();
    scatter_kernel<<<(NE + 255) / 256, 256>>>(src, dst);

    dim3 g128(1, (NN + 127) / 128);
    dim3 g32(1, (NN + 127) / 128);
    int aggBlocks = (NN + 7) / 8;

    // ---- layer 0 ----
    sgemm_kernel<128, 128, 16, 8, 8><<<g128, 256>>>(x, SEL_EXT, W0, nullptr, nullptr, SEL_HPROJ, NN, HC, FIN);
    sgemm_kernel<128, 128, 16, 8, 8><<<g128, 256>>>(x, SEL_EXT, Ws0, bs0, nullptr, SEL_HSKIP, NN, HC, FIN);
    al_kernel<<<(NN * NH + 255) / 256, 256>>>(aS0, aD0);
    agg_kernel<<<aggBlocks, 256>>>(SEL_HSKIP, b0, nullptr, SEL_FEAT1, 0);

    // ---- layer 1 ----
    sgemm_kernel<128, 128, 16, 8, 8><<<g128, 256>>>(nullptr, SEL_FEAT1, W1, nullptr, nullptr, SEL_HPROJ, NN, HC, HC);
    sgemm_kernel<128, 128, 16, 8, 8><<<g128, 256>>>(nullptr, SEL_FEAT1, Ws1, bs1, nullptr, SEL_HSKIP, NN, HC, HC);
    al_kernel<<<(NN * NH + 255) / 256, 256>>>(aS1, aD1);
    agg_kernel<<<aggBlocks, 256>>>(SEL_HSKIP, b1, nullptr, SEL_FEAT2, 0);

    // ---- layer 2 ----
    sgemm_kernel<128, 128, 16, 8, 8><<<g128, 256>>>(nullptr, SEL_FEAT2, W2, nullptr, nullptr, SEL_HPROJ, NN, HC, HC);
    sgemm_kernel<128, 32, 32, 8, 4><<<g32, 128>>>(nullptr, SEL_FEAT2, Ws2, bs2, nullptr, SEL_HSKIP32, NN, NOUT, HC);
    al_kernel<<<(NN * NH + 255) / 256, 256>>>(aS2, aD2);
    agg_kernel<<<aggBlocks, 256>>>(SEL_HSKIP32, b2, out, SEL_EXT, 1);
}

// round 4
// speedup vs baseline: 1.2019x; 1.2019x over previous
#include <cuda_runtime.h>
#include <cuda_bf16.h>
#include <cstdint>

#define NN 50000
#define NE 800000
#define FIN 128
#define HC 128      // HEADS*HID = 4*32
#define NH 4
#define CH 32
#define NOUT 32

// ------------------------- device scratch (no allocation allowed) -------------------------
__device__ float g_hproj[(size_t)NN * HC];
__device__ float g_hskip[(size_t)NN * HC];
__device__ float g_feat1[(size_t)NN * HC];
__device__ float g_feat2[(size_t)NN * HC];
__device__ float g_hskip32[(size_t)NN * NOUT];
__device__ float g_als[(size_t)NN * NH];
__device__ float g_ald[(size_t)NN * NH];
__device__ int   g_deg[NN];
__device__ int   g_cursor[NN];
__device__ int   g_rowptr[NN + 1];
__device__ int   g_csr[NE];

#define SEL_EXT     0
#define SEL_HPROJ   1
#define SEL_HSKIP   2
#define SEL_FEAT1   3
#define SEL_FEAT2   4
#define SEL_HSKIP32 5

__device__ __forceinline__ float* selbuf(int sel, float* ext) {
    switch (sel) {
        case SEL_HPROJ:   return g_hproj;
        case SEL_HSKIP:   return g_hskip;
        case SEL_FEAT1:   return g_feat1;
        case SEL_FEAT2:   return g_feat2;
        case SEL_HSKIP32: return g_hskip32;
        default:          return ext;
    }
}
__device__ __forceinline__ const float* selbuf_c(int sel, const float* ext) {
    return selbuf(sel, (float*)ext);
}

// ------------------------- f32x2 packed math helpers -------------------------
__device__ __forceinline__ unsigned long long pk2(float x, float y) {
    unsigned long long r;
    asm("mov.b64 %0,{%1,%2};" : "=l"(r) : "f"(x), "f"(y));
    return r;
}
__device__ __forceinline__ void upk2(unsigned long long v, float& x, float& y) {
    asm("mov.b64 {%0,%1},%2;" : "=f"(x), "=f"(y) : "l"(v));
}
__device__ __forceinline__ unsigned long long ffma2(unsigned long long a, unsigned long long b,
                                                    unsigned long long c) {
    unsigned long long d;
    asm("fma.rn.f32x2 %0,%1,%2,%3;" : "=l"(d) : "l"(a), "l"(b), "l"(c));
    return d;
}

// ------------------------- CSR build -------------------------
__global__ void zero_kernel() {
    int i = blockIdx.x * blockDim.x + threadIdx.x;
    if (i < NN) { g_deg[i] = 0; g_cursor[i] = 0; }
}

__global__ void count_kernel(const int* __restrict__ dst) {
    int i = blockIdx.x * blockDim.x + threadIdx.x;
    if (i < NE) atomicAdd(&g_deg[dst[i]], 1);
}

// exclusive scan of g_deg into g_rowptr, g_rowptr[NN]=total. Single block.
__global__ void scan_kernel() {
    __shared__ int sh[1024];
    __shared__ int carry;
    if (threadIdx.x == 0) carry = 0;
    __syncthreads();
    for (int base = 0; base < NN; base += 1024) {
        int i = base + threadIdx.x;
        int v = (i < NN) ? g_deg[i] : 0;
        sh[threadIdx.x] = v;
        __syncthreads();
        for (int off = 1; off < 1024; off <<= 1) {
            int t = 0;
            if ((int)threadIdx.x >= off) t = sh[threadIdx.x - off];
            __syncthreads();
            sh[threadIdx.x] += t;
            __syncthreads();
        }
        if (i < NN) g_rowptr[i] = carry + sh[threadIdx.x] - v;
        __syncthreads();
        if (threadIdx.x == 0) carry += sh[1023];
        __syncthreads();
    }
    if (threadIdx.x == 0) g_rowptr[NN] = carry;
}

__global__ void scatter_kernel(const int* __restrict__ src, const int* __restrict__ dst) {
    int i = blockIdx.x * blockDim.x + threadIdx.x;
    if (i < NE) {
        int d = dst[i];
        int pos = g_rowptr[d] + atomicAdd(&g_cursor[d], 1);
        g_csr[pos] = src[i];
    }
}

// ------------------------- SGEMM (f32x2, double-buffered) -------------------------
// C[M,N] = A[M,K] @ B[K,N] (+ bias[N] if bias != nullptr). K,N multiples of BK/BN.
template <int BM, int BN, int BK, int TM, int TN>
__global__ void __launch_bounds__((BM / TM) * (BN / TN), 2)
sgemm_kernel(const float* __restrict__ Aext, int Asel,
             const float* __restrict__ B,
             const float* __restrict__ bias,
             float* __restrict__ Cext, int Csel,
             int M, int N, int K) {
    const float* A = selbuf_c(Asel, Aext);
    float* C = selbuf(Csel, Cext);
    constexpr int NT = (BM / TM) * (BN / TN);
    constexpr int AR = (BM * BK) / (4 * NT);   // float4 A loads per thread
    constexpr int BR = (BK * BN) / (4 * NT);   // float4 B loads per thread
    static_assert(AR >= 1 && BR >= 1, "tile too small");

    __shared__ float As[2][BK][BM + 4];
    __shared__ float Bs[2][BK][BN];

    int tid = threadIdx.x;
    int m0 = blockIdx.y * BM;
    int n0 = blockIdx.x * BN;
    int tx = tid % (BN / TN);
    int ty = tid / (BN / TN);

    unsigned long long acc[TM][TN / 2];
#pragma unroll
    for (int i = 0; i < TM; i++)
#pragma unroll
        for (int j = 0; j < TN / 2; j++) acc[i][j] = 0ull;

    float4 pa[AR], pb[BR];

    auto fetch = [&](int k0) {
#pragma unroll
        for (int it = 0; it < AR; it++) {
            int idx = tid + it * NT;
            int r = idx / (BK / 4);
            int c = (idx % (BK / 4)) * 4;
            pa[it] = (m0 + r < M) ? *(const float4*)&A[(size_t)(m0 + r) * K + k0 + c]
                                  : make_float4(0.f, 0.f, 0.f, 0.f);
        }
#pragma unroll
        for (int it = 0; it < BR; it++) {
            int idx = tid + it * NT;
            int r = idx / (BN / 4);
            int c = (idx % (BN / 4)) * 4;
            pb[it] = *(const float4*)&B[(size_t)(k0 + r) * N + n0 + c];
        }
    };
    auto stage = [&](int buf) {
#pragma unroll
        for (int it = 0; it < AR; it++) {
            int idx = tid + it * NT;
            int r = idx / (BK / 4);
            int c = (idx % (BK / 4)) * 4;
            As[buf][c + 0][r] = pa[it].x;
            As[buf][c + 1][r] = pa[it].y;
            As[buf][c + 2][r] = pa[it].z;
            As[buf][c + 3][r] = pa[it].w;
        }
#pragma unroll
        for (int it = 0; it < BR; it++) {
            int idx = tid + it * NT;
            int r = idx / (BN / 4);
            int c = (idx % (BN / 4)) * 4;
            *(float4*)&Bs[buf][r][c] = pb[it];
        }
    };

    fetch(0);
    stage(0);
    __syncthreads();

    int nb = K / BK;
    for (int t = 0; t < nb; t++) {
        if (t + 1 < nb) fetch((t + 1) * BK);
        int cur = t & 1;
#pragma unroll
        for (int k = 0; k < BK; k++) {
            unsigned long long a2[TM];
#pragma unroll
            for (int i = 0; i < TM; i += 4) {
                float4 av = *(const float4*)&As[cur][k][ty * TM + i];
                a2[i + 0] = pk2(av.x, av.x);
                a2[i + 1] = pk2(av.y, av.y);
                a2[i + 2] = pk2(av.z, av.z);
                a2[i + 3] = pk2(av.w, av.w);
            }
            unsigned long long b2[TN / 2];
#pragma unroll
            for (int j = 0; j < TN; j += 4) {
                ulonglong2 bv = *(const ulonglong2*)&Bs[cur][k][tx * TN + j];
                b2[j / 2 + 0] = bv.x;
                b2[j / 2 + 1] = bv.y;
            }
#pragma unroll
            for (int i = 0; i < TM; i++)
#pragma unroll
                for (int j = 0; j < TN / 2; j++) acc[i][j] = ffma2(a2[i], b2[j], acc[i][j]);
        }
        if (t + 1 < nb) {
            stage((t + 1) & 1);
            __syncthreads();
        }
    }

#pragma unroll
    for (int i = 0; i < TM; i++) {
        int row = m0 + ty * TM + i;
        if (row < M) {
#pragma unroll
            for (int j = 0; j < TN / 2; j++) {
                int col = n0 + tx * TN + 2 * j;
                float c0, c1;
                upk2(acc[i][j], c0, c1);
                if (bias) {
                    c0 += __ldg(&bias[col]);
                    c1 += __ldg(&bias[col + 1]);
                }
                *(float2*)&C[(size_t)row * N + col] = make_float2(c0, c1);
            }
        }
    }
}

// ------------------------- attention logits -------------------------
__global__ void al_kernel(const float* __restrict__ aS, const float* __restrict__ aD) {
    int idx = blockIdx.x * blockDim.x + threadIdx.x;
    if (idx >= NN * NH) return;
    int n = idx >> 2;
    int h = idx & 3;
    const float* hp = &g_hproj[(size_t)n * HC + h * CH];
    const float* as = &aS[h * CH];
    const float* ad = &aD[h * CH];
    float s1 = 0.f, s2 = 0.f;
#pragma unroll
    for (int c = 0; c < CH; c += 4) {
        float4 hv = *(const float4*)&hp[c];
        float4 av = __ldg((const float4*)&as[c]);
        float4 dv = __ldg((const float4*)&ad[c]);
        s1 += hv.x * av.x + hv.y * av.y + hv.z * av.z + hv.w * av.w;
        s2 += hv.x * dv.x + hv.y * dv.y + hv.z * dv.z + hv.w * dv.w;
    }
    g_als[idx] = s1;
    g_ald[idx] = s2;
}

__device__ __forceinline__ float lrelu(float x) { return x > 0.f ? x : 0.2f * x; }

// ------------------------- aggregation (softmax + weighted sum) -------------------------
__global__ void agg_kernel(int skipsel, const float* __restrict__ bias,
                           float* __restrict__ outext, int outsel, int mode) {
    const float* hskip = selbuf_c(skipsel, nullptr);
    float* outp = selbuf(outsel, outext);
    const int WPB = 8;
    __shared__ float sh_alpha[WPB][32][4];
    __shared__ int sh_src[WPB][32];
    int w = threadIdx.x >> 5;
    int lane = threadIdx.x & 31;
    int n = blockIdx.x * WPB + w;
    if (n >= NN) return;
    int beg = g_rowptr[n], end = g_rowptr[n + 1];
    float4 ad = *(const float4*)&g_ald[(size_t)n * 4];

    // pass 1: per-head max
    float mx0 = -1e30f, mx1 = -1e30f, mx2 = -1e30f, mx3 = -1e30f;
    for (int j = beg + lane; j < end; j += 32) {
        int s = __ldg(&g_csr[j]);
        float4 a = __ldg((const float4*)&g_als[(size_t)s * 4]);
        mx0 = fmaxf(mx0, lrelu(a.x + ad.x));
        mx1 = fmaxf(mx1, lrelu(a.y + ad.y));
        mx2 = fmaxf(mx2, lrelu(a.z + ad.z));
        mx3 = fmaxf(mx3, lrelu(a.w + ad.w));
    }
#pragma unroll
    for (int o = 16; o > 0; o >>= 1) {
        mx0 = fmaxf(mx0, __shfl_xor_sync(0xffffffffu, mx0, o));
        mx1 = fmaxf(mx1, __shfl_xor_sync(0xffffffffu, mx1, o));
        mx2 = fmaxf(mx2, __shfl_xor_sync(0xffffffffu, mx2, o));
        mx3 = fmaxf(mx3, __shfl_xor_sync(0xffffffffu, mx3, o));
    }
    // pass 2: sum of exp
    float s0 = 0.f, s1 = 0.f, s2 = 0.f, s3 = 0.f;
    for (int j = beg + lane; j < end; j += 32) {
        int s = __ldg(&g_csr[j]);
        float4 a = __ldg((const float4*)&g_als[(size_t)s * 4]);
        s0 += __expf(lrelu(a.x + ad.x) - mx0);
        s1 += __expf(lrelu(a.y + ad.y) - mx1);
        s2 += __expf(lrelu(a.z + ad.z) - mx2);
        s3 += __expf(lrelu(a.w + ad.w) - mx3);
    }
#pragma unroll
    for (int o = 16; o > 0; o >>= 1) {
        s0 += __shfl_xor_sync(0xffffffffu, s0, o);
        s1 += __shfl_xor_sync(0xffffffffu, s1, o);
        s2 += __shfl_xor_sync(0xffffffffu, s2, o);
        s3 += __shfl_xor_sync(0xffffffffu, s3, o);
    }
    float inv0 = 1.f / (s0 + 1e-16f);
    float inv1 = 1.f / (s1 + 1e-16f);
    float inv2 = 1.f / (s2 + 1e-16f);
    float inv3 = 1.f / (s3 + 1e-16f);

    // pass 3: weighted gather of hproj[src]
    float acc0 = 0.f, acc1 = 0.f, acc2 = 0.f, acc3 = 0.f;
    for (int base = beg; base < end; base += 32) {
        int j = base + lane;
        if (j < end) {
            int sr = g_csr[j];
            sh_src[w][lane] = sr;
            float4 a = __ldg((const float4*)&g_als[(size_t)sr * 4]);
            sh_alpha[w][lane][0] = __expf(lrelu(a.x + ad.x) - mx0) * inv0;
            sh_alpha[w][lane][1] = __expf(lrelu(a.y + ad.y) - mx1) * inv1;
            sh_alpha[w][lane][2] = __expf(lrelu(a.z + ad.z) - mx2) * inv2;
            sh_alpha[w][lane][3] = __expf(lrelu(a.w + ad.w) - mx3) * inv3;
        }
        __syncwarp();
        int cnt = min(32, end - base);
        for (int k = 0; k < cnt; k++) {
            int sr = sh_src[w][k];
            const float* hp = &g_hproj[(size_t)sr * HC];
            float a0 = sh_alpha[w][k][0];
            float a1 = sh_alpha[w][k][1];
            float a2 = sh_alpha[w][k][2];
            float a3 = sh_alpha[w][k][3];
            acc0 += a0 * hp[lane];
            acc1 += a1 * hp[32 + lane];
            acc2 += a2 * hp[64 + lane];
            acc3 += a3 * hp[96 + lane];
        }
        __syncwarp();
    }

    if (mode == 0) {
        float accs[4] = {acc0, acc1, acc2, acc3};
#pragma unroll
        for (int h = 0; h < 4; h++) {
            int c = h * 32 + lane;
            float v = accs[h] + __ldg(&bias[c]) + hskip[(size_t)n * HC + c];
            v = v > 0.f ? v : expm1f(v);
            outp[(size_t)n * HC + c] = v;
        }
    } else {
        float v = 0.25f * (acc0 + acc1 + acc2 + acc3) + __ldg(&bias[lane]) +
                  hskip[(size_t)n * NOUT + lane];
        float ss = v * v;
#pragma unroll
        for (int o = 16; o > 0; o >>= 1) ss += __shfl_xor_sync(0xffffffffu, ss, o);
        float r = sqrtf(ss);
        outp[(size_t)n * NOUT + lane] = v / fmaxf(r, 1e-12f);
    }
}

// ------------------------- launch -------------------------
extern "C" void kernel_launch(void* const* d_in, const int* in_sizes, int n_in,
                              void* d_out, int out_size) {
    const float* x = (const float*)d_in[0];
    const int* ei = (const int*)d_in[1];
    const int* src = ei;
    const int* dst = ei + NE;
    const float* W0 = (const float*)d_in[2];
    const float* aS0 = (const float*)d_in[3];
    const float* aD0 = (const float*)d_in[4];
    const float* b0 = (const float*)d_in[5];
    const float* Ws0 = (const float*)d_in[6];
    const float* bs0 = (const float*)d_in[7];
    const float* W1 = (const float*)d_in[8];
    const float* aS1 = (const float*)d_in[9];
    const float* aD1 = (const float*)d_in[10];
    const float* b1 = (const float*)d_in[11];
    const float* Ws1 = (const float*)d_in[12];
    const float* bs1 = (const float*)d_in[13];
    const float* W2 = (const float*)d_in[14];
    const float* aS2 = (const float*)d_in[15];
    const float* aD2 = (const float*)d_in[16];
    const float* b2 = (const float*)d_in[17];
    const float* Ws2 = (const float*)d_in[18];
    const float* bs2 = (const float*)d_in[19];
    float* out = (float*)d_out;

    // ---- CSR build ----
    zero_kernel<<<(NN + 255) / 256, 256>>>();
    count_kernel<<<(NE + 255) / 256, 256>>>(dst);
    scan_kernel<<<1, 1024>>>();
    scatter_kernel<<<(NE + 255) / 256, 256>>>(src, dst);

    dim3 g128(1, (NN + 127) / 128);
    int aggBlocks = (NN + 7) / 8;

    // ---- layer 0 ----
    sgemm_kernel<128, 128, 16, 8, 8><<<g128, 256>>>(x, SEL_EXT, W0, nullptr, nullptr, SEL_HPROJ, NN, HC, FIN);
    sgemm_kernel<128, 128, 16, 8, 8><<<g128, 256>>>(x, SEL_EXT, Ws0, bs0, nullptr, SEL_HSKIP, NN, HC, FIN);
    al_kernel<<<(NN * NH + 255) / 256, 256>>>(aS0, aD0);
    agg_kernel<<<aggBlocks, 256>>>(SEL_HSKIP, b0, nullptr, SEL_FEAT1, 0);

    // ---- layer 1 ----
    sgemm_kernel<128, 128, 16, 8, 8><<<g128, 256>>>(nullptr, SEL_FEAT1, W1, nullptr, nullptr, SEL_HPROJ, NN, HC, HC);
    sgemm_kernel<128, 128, 16, 8, 8><<<g128, 256>>>(nullptr, SEL_FEAT1, Ws1, bs1, nullptr, SEL_HSKIP, NN, HC, HC);
    al_kernel<<<(NN * NH + 255) / 256, 256>>>(aS1, aD1);
    agg_kernel<<<aggBlocks, 256>>>(SEL_HSKIP, b1, nullptr, SEL_FEAT2, 0);

    // ---- layer 2 ----
    sgemm_kernel<128, 128, 16, 8, 8><<<g128, 256>>>(nullptr, SEL_FEAT2, W2, nullptr, nullptr, SEL_HPROJ, NN, HC, HC);
    sgemm_kernel<128, 32, 16, 8, 4><<<dim3(1, (NN + 127) / 128), 128>>>(nullptr, SEL_FEAT2, Ws2, bs2, nullptr, SEL_HSKIP32, NN, NOUT, HC);
    al_kernel<<<(NN * NH + 255) / 256, 256>>>(aS2, aD2);
    agg_kernel<<<aggBlocks, 256>>>(SEL_HSKIP32, b2, out, SEL_EXT, 1);
}